// round 16
// baseline (speedup 1.0000x reference)
#include <cuda_runtime.h>
#include <cuda_bf16.h>
#include <cuda_fp16.h>
#include <cstdint>
#include <math.h>

// ============================================================================
// MLP: out[e] = gelu_tanh(x[e] @ w1[e]) @ w2[e]
//   E=8, T=2048, H=1024, F=4096, fp32 in/out.
// Both GEMMs single-product fp16 (calibrated err: 4 rounding events ~4.2e-4).
// R16: GEMM mainloop = R12 verbatim (warp 64x64, 128-thr CTA, 3x32KB stages,
//   2 CTAs/SM, 846us baseline). B operand now consumed in NATIVE [K,N]
//   row-major via ldmatrix.m8n8.x4.trans + per-row chunk swizzle (c ^= k&7),
//   eliminating both weight-transpose pre-pass kernels (w1=[H,F], w2=[F,H]
//   are already [K,N] for their GEMMs). Pre-pass = 3 streaming converts.
// ============================================================================

static constexpr int E_ = 8, T_ = 2048, H_ = 1024, F_ = 4096;

// -------- static device scratch --------
__device__ __half g_x16[(size_t)E_ * T_ * H_];        // x fp16 [T,H]
__device__ __half g_w1f[(size_t)E_ * H_ * F_];        // w1 fp16 [H,F] (=K,N)
__device__ __half g_w2f[(size_t)E_ * F_ * H_];        // w2 fp16 [F,H] (=K,N)
__device__ __half g_h16[(size_t)E_ * T_ * F_];        // gelu(x@w1) fp16 [T,F]

// -------- helpers --------
__device__ __forceinline__ uint32_t smem_u32(const void* p) {
    return (uint32_t)__cvta_generic_to_shared(p);
}
__device__ __forceinline__ void cp16(uint32_t s, const void* g) {
    asm volatile("cp.async.cg.shared.global [%0], [%1], 16;\n"
                 :: "r"(s), "l"(__cvta_generic_to_global(g)));
}
__device__ __forceinline__ void cp_commit() {
    asm volatile("cp.async.commit_group;\n" ::: "memory");
}
template <int N> __device__ __forceinline__ void cp_wait() {
    asm volatile("cp.async.wait_group %0;\n" :: "n"(N) : "memory");
}
#define SWZ(x) ((x) ^ (((x) >> 3) & 0x70))

#define LDSM_X4(r0, r1, r2, r3, a)                                          \
    asm volatile("ldmatrix.sync.aligned.m8n8.x4.shared.b16 {%0,%1,%2,%3}, [%4];" \
                 : "=r"(r0), "=r"(r1), "=r"(r2), "=r"(r3) : "r"(a))

#define LDSM_X4_T(r0, r1, r2, r3, a)                                        \
    asm volatile("ldmatrix.sync.aligned.m8n8.x4.trans.shared.b16 {%0,%1,%2,%3}, [%4];" \
                 : "=r"(r0), "=r"(r1), "=r"(r2), "=r"(r3) : "r"(a))

__device__ __forceinline__ void mma16816(float* c, const uint32_t* a, const uint32_t* b) {
    asm volatile(
        "mma.sync.aligned.m16n8k16.row.col.f32.f16.f16.f32 "
        "{%0,%1,%2,%3}, {%4,%5,%6,%7}, {%8,%9}, {%0,%1,%2,%3};\n"
        : "+f"(c[0]), "+f"(c[1]), "+f"(c[2]), "+f"(c[3])
        : "r"(a[0]), "r"(a[1]), "r"(a[2]), "r"(a[3]), "r"(b[0]), "r"(b[1]));
}

__device__ __forceinline__ float gelu_tanh_f(float x) {
    float inner = 0.7978845608028654f * (x + 0.044715f * x * x * x);
    return 0.5f * x * (1.0f + tanhf(inner));
}

// -------- pre-pass: fp32 -> fp16 streaming convert --------
__global__ void conv16_k(const float* __restrict__ in, __half* __restrict__ o, size_t n4) {
    size_t i = (size_t)blockIdx.x * blockDim.x + threadIdx.x;
    if (i >= n4) return;
    float4 v = ((const float4*)in)[i];
    __half2 a = __floats2half2_rn(v.x, v.y);
    __half2 b = __floats2half2_rn(v.z, v.w);
    ((uint2*)o)[i] = make_uint2(*(uint32_t*)&a, *(uint32_t*)&b);
}

// -------- warp-mma GEMM: C[M,N] = A[M,K] @ B[K,N], single fp16 ------------
// A: [M,K] row-major, SW128-swizzled 128B rows.
// B: [K,N] row-major, 256B rows (128 halves), chunk swizzle c ^= (k&7),
//    fragments via ldmatrix.trans.
#define CTA_M 128
#define CTA_N 128
#define CTA_K 64
#define NTHREADS 128
#define ARR_BYTES (128 * 128)       // A: 128 rows x 128B; B: 64 rows x 256B = same 16 KB
#define STAGE_BYTES (2 * ARR_BYTES) // A, B = 32 KB
#define NSTAGES 3
#define SMEM_TOTAL (NSTAGES * STAGE_BYTES)  // 96 KB -> 2 CTAs/SM

template <bool FUSE_GELU>
__global__ __launch_bounds__(NTHREADS, 2)
void gemm_wm(const __half* __restrict__ A0, const __half* __restrict__ B0,
             float* __restrict__ Cf, __half* __restrict__ Ch,
             int M, int N, int K) {
    extern __shared__ __align__(1024) char smem[];
    uint32_t sb = smem_u32(smem);
    const int tid = threadIdx.x, warp = tid >> 5, lid = tid & 31;
    const int e = blockIdx.z;
    const int m0 = blockIdx.y * CTA_M, n0 = blockIdx.x * CTA_N;
    const int wm = (warp >> 1) * 64;    // 2 warp rows x 64
    const int wn = (warp & 1) * 64;     // 2 warp cols x 64
    const int g = lid >> 2, q = lid & 3;

    size_t eA = (size_t)e * M * K, eB = (size_t)e * K * N;
    const __half* gA = A0 + eA + (size_t)m0 * K;
    const __half* gB = B0 + eB + n0;          // column offset; rows stride N

    float acc[4][8][4];
#pragma unroll
    for (int mi = 0; mi < 4; mi++)
#pragma unroll
        for (int ni = 0; ni < 8; ni++)
#pragma unroll
            for (int k2 = 0; k2 < 4; k2++) acc[mi][ni][k2] = 0.0f;

    auto load_stage = [&](int kt, int s) {
        uint32_t st = sb + s * STAGE_BYTES;
        int k0 = kt * CTA_K;
#pragma unroll
        for (int i = 0; i < 8; i++) {
            int c = i * NTHREADS + tid;
            // A: 1024 chunks; chunk c -> row = c>>3, 16B chunk h = c&7
            {
                int row = c >> 3, h = c & 7;
                uint32_t sw = SWZ((uint32_t)(row * 128 + h * 16));
                cp16(st + sw, gA + (size_t)row * K + k0 + h * 8);
            }
            // B: 1024 chunks; chunk c -> k-row = c>>4, 16B chunk cn = c&15
            {
                int kr = c >> 4, cn = c & 15;
                uint32_t sw = (uint32_t)(kr * 256 + ((cn ^ (kr & 7)) << 4));
                cp16(st + ARR_BYTES + sw, gB + (size_t)(k0 + kr) * N + cn * 8);
            }
        }
    };

    auto compute = [&](int s) {
        uint32_t aA = sb + s * STAGE_BYTES;
        uint32_t bB = aA + ARR_BYTES;
        // lane roles for B trans-load: tile t = lid>>3 (k-half, n-half), r = lid&7
        const int bt = lid >> 3, br = lid & 7;
        const int b_khalf = (bt & 1) * 8;         // +0 / +8 in k
        const int b_nhalf = (bt >> 1) * 8;        // +0 / +8 in n
#pragma unroll
        for (int kk = 0; kk < CTA_K; kk += 16) {
            uint32_t av[4][4], bb[8][2];
            // A fragments (unchanged from R12)
            {
                int arow = wm + (lid & 15);
                uint32_t acol = (uint32_t)(kk * 2 + (lid >> 4) * 16);
#pragma unroll
                for (int mi = 0; mi < 4; mi++) {
                    uint32_t ad = SWZ((uint32_t)((arow + mi * 16) * 128) + acol);
                    LDSM_X4(av[mi][0], av[mi][1], av[mi][2], av[mi][3], aA + ad);
                }
            }
            // B fragments from [K,N] tile via ldmatrix.trans
            {
                int k_local = kk + b_khalf + br;               // row in B tile
#pragma unroll
                for (int nf = 0; nf < 4; nf++) {
                    int n_local = wn + nf * 16 + b_nhalf;      // multiple of 8
                    uint32_t ad = (uint32_t)(k_local * 256 +
                                  ((((n_local >> 3) ^ (k_local & 7)) & 15) << 4));
                    LDSM_X4_T(bb[nf * 2][0], bb[nf * 2][1],
                              bb[nf * 2 + 1][0], bb[nf * 2 + 1][1], bB + ad);
                }
            }
#pragma unroll
            for (int mi = 0; mi < 4; mi++)
#pragma unroll
                for (int ni = 0; ni < 8; ni++) mma16816(acc[mi][ni], av[mi], bb[ni]);
        }
    };

    const int NK = K / CTA_K;
    load_stage(0, 0);
    cp_commit();
    load_stage(1, 1);
    cp_commit();

    for (int kt = 0; kt < NK; kt++) {
        int s = kt % NSTAGES;
        cp_wait<1>();           // stage kt loads complete (1 younger group pending)
        __syncthreads();        // data visible; next-load stage free (compute(kt-1) done)
        if (kt + 2 < NK) load_stage(kt + 2, (kt + 2) % NSTAGES);
        cp_commit();            // commit every iter (possibly empty) to keep count
        compute(s);
    }

    // ---- epilogue ----
#pragma unroll
    for (int mi = 0; mi < 4; mi++) {
#pragma unroll
        for (int ni = 0; ni < 8; ni++) {
            int r = m0 + wm + mi * 16 + g;
            int col = n0 + wn + ni * 8 + q * 2;
            size_t o0 = ((size_t)e * M + r) * N + col;
            size_t o1 = o0 + (size_t)8 * N;
            float v0 = acc[mi][ni][0], v1 = acc[mi][ni][1];
            float v2 = acc[mi][ni][2], v3 = acc[mi][ni][3];
            if (FUSE_GELU) {
                v0 = gelu_tanh_f(v0); v1 = gelu_tanh_f(v1);
                v2 = gelu_tanh_f(v2); v3 = gelu_tanh_f(v3);
                __half2 p0 = __floats2half2_rn(v0, v1);
                __half2 p1 = __floats2half2_rn(v2, v3);
                *(__half2*)(Ch + o0) = p0;
                *(__half2*)(Ch + o1) = p1;
            } else {
                *(float2*)(Cf + o0) = make_float2(v0, v1);
                *(float2*)(Cf + o1) = make_float2(v2, v3);
            }
        }
    }
}

// -------- host launch --------
extern "C" void kernel_launch(void* const* d_in, const int* in_sizes, int n_in,
                              void* d_out, int out_size) {
    const float* x = (const float*)d_in[0];
    const float* w1 = (const float*)d_in[1];
    const float* w2 = (const float*)d_in[2];
    float* out = (float*)d_out;

    __half *x16, *w1f, *w2f, *h16;
    cudaGetSymbolAddress((void**)&x16, g_x16);
    cudaGetSymbolAddress((void**)&w1f, g_w1f);
    cudaGetSymbolAddress((void**)&w2f, g_w2f);
    cudaGetSymbolAddress((void**)&h16, g_h16);

    cudaFuncSetAttribute(gemm_wm<true>, cudaFuncAttributeMaxDynamicSharedMemorySize, SMEM_TOTAL);
    cudaFuncSetAttribute(gemm_wm<false>, cudaFuncAttributeMaxDynamicSharedMemorySize, SMEM_TOTAL);

    // pre-pass: three streaming fp32->fp16 converts (no transposes)
    size_t nx4 = (size_t)E_ * T_ * H_ / 4;
    size_t nw4 = (size_t)E_ * H_ * F_ / 4;
    conv16_k<<<(unsigned)((nx4 + 255) / 256), 256>>>(x, x16, nx4);
    conv16_k<<<(unsigned)((nw4 + 255) / 256), 256>>>(w1, w1f, nw4);
    conv16_k<<<(unsigned)((nw4 + 255) / 256), 256>>>(w2, w2f, nw4);

    // GEMM1 + GELU: A=x fp16 [T,H], B=w1 fp16 [H,F] -> h fp16 [T,F]
    gemm_wm<true><<<dim3(F_ / CTA_N, T_ / CTA_M, E_), NTHREADS, SMEM_TOTAL>>>(
        x16, w1f, nullptr, h16, T_, F_, H_);
    // GEMM2: A=h fp16 [T,F], B=w2 fp16 [F,H] -> out fp32 [T,H]
    gemm_wm<false><<<dim3(H_ / CTA_N, T_ / CTA_M, E_), NTHREADS, SMEM_TOTAL>>>(
        h16, w2f, out, nullptr, T_, H_, F_);
}

// round 17
// speedup vs baseline: 1.4151x; 1.4151x over previous
#include <cuda_runtime.h>
#include <cuda_bf16.h>
#include <cuda_fp16.h>
#include <cstdint>
#include <math.h>

// ============================================================================
// MLP: out[e] = gelu_tanh(x[e] @ w1[e]) @ w2[e]
//   E=8, T=2048, H=1024, F=4096, fp32 in/out.
// Both GEMMs single-product fp16 (calibrated err: 4 rounding events ~4.2e-4).
// R17: GEMM = R12 verbatim (warp 64x64, 128-thr CTA, 3x32KB stages,
//   2 CTAs/SM — verified 846us optimum; trans-B / 3-CTA / prefetch variants
//   all measured worse). Pre-pass consolidated: x convert + ONE fused
//   dual-weight transpose kernel (z selects w1/w2), 64 cols per block.
// ============================================================================

static constexpr int E_ = 8, T_ = 2048, H_ = 1024, F_ = 4096;

// -------- static device scratch --------
__device__ __half g_x16[(size_t)E_ * T_ * H_];        // x fp16
__device__ __half g_w1t[(size_t)E_ * F_ * H_];        // w1^T: [E,F,H] fp16
__device__ __half g_w2t[(size_t)E_ * H_ * F_];        // w2^T: [E,H,F] fp16
__device__ __half g_h16[(size_t)E_ * T_ * F_];        // gelu(x@w1) fp16

// -------- helpers --------
__device__ __forceinline__ uint32_t smem_u32(const void* p) {
    return (uint32_t)__cvta_generic_to_shared(p);
}
__device__ __forceinline__ void cp16(uint32_t s, const void* g) {
    asm volatile("cp.async.cg.shared.global [%0], [%1], 16;\n"
                 :: "r"(s), "l"(__cvta_generic_to_global(g)));
}
__device__ __forceinline__ void cp_commit() {
    asm volatile("cp.async.commit_group;\n" ::: "memory");
}
template <int N> __device__ __forceinline__ void cp_wait() {
    asm volatile("cp.async.wait_group %0;\n" :: "n"(N) : "memory");
}
#define SWZ(x) ((x) ^ (((x) >> 3) & 0x70))

#define LDSM_X4(r0, r1, r2, r3, a)                                          \
    asm volatile("ldmatrix.sync.aligned.m8n8.x4.shared.b16 {%0,%1,%2,%3}, [%4];" \
                 : "=r"(r0), "=r"(r1), "=r"(r2), "=r"(r3) : "r"(a))

__device__ __forceinline__ void mma16816(float* c, const uint32_t* a, const uint32_t* b) {
    asm volatile(
        "mma.sync.aligned.m16n8k16.row.col.f32.f16.f16.f32 "
        "{%0,%1,%2,%3}, {%4,%5,%6,%7}, {%8,%9}, {%0,%1,%2,%3};\n"
        : "+f"(c[0]), "+f"(c[1]), "+f"(c[2]), "+f"(c[3])
        : "r"(a[0]), "r"(a[1]), "r"(a[2]), "r"(a[3]), "r"(b[0]), "r"(b[1]));
}

__device__ __forceinline__ float gelu_tanh_f(float x) {
    float inner = 0.7978845608028654f * (x + 0.044715f * x * x * x);
    return 0.5f * x * (1.0f + tanhf(inner));
}

// -------- pre-pass: fp32 -> fp16 convert (x) --------
__global__ void conv16_k(const float* __restrict__ in, __half* __restrict__ o, size_t n4) {
    size_t i = (size_t)blockIdx.x * blockDim.x + threadIdx.x;
    if (i >= n4) return;
    float4 v = ((const float4*)in)[i];
    __half2 a = __floats2half2_rn(v.x, v.y);
    __half2 b = __floats2half2_rn(v.z, v.w);
    ((uint2*)o)[i] = make_uint2(*(uint32_t*)&a, *(uint32_t*)&b);
}

// -------- pre-pass: fused dual-weight transpose+convert ------------------
// z in [0, 2E): z < E -> w1 ([H,F] -> [F,H]), else w2 ([F,H] -> [H,F]).
// Each block handles a 32-row x 64-col tile (two 32x32 sub-tiles).
__global__ void tconv2(const float* __restrict__ w1, const float* __restrict__ w2,
                       __half* __restrict__ o1, __half* __restrict__ o2) {
    __shared__ float t[32][33];
    const bool is_w1 = (blockIdx.z < E_);
    const int e = is_w1 ? blockIdx.z : (blockIdx.z - E_);
    const int R = is_w1 ? H_ : F_;
    const int C = is_w1 ? F_ : H_;
    const float* ip = (is_w1 ? w1 : w2) + (size_t)e * R * C;
    __half* op = (is_w1 ? o1 : o2) + (size_t)e * R * C;
    const int cblocks = C / 64;
    const int b = blockIdx.x;
    const int c0 = (b % cblocks) * 64, r0 = (b / cblocks) * 32;
    const int tx = threadIdx.x, ty = threadIdx.y;
    const int idx = ty * 32 + tx;    // 0..255
    const int cc = idx >> 3;         // 0..31
    const int rr = (idx & 7) * 4;    // 0,4,..,28

#pragma unroll
    for (int half = 0; half < 2; half++) {
        int ch = c0 + half * 32;
        for (int j = ty; j < 32; j += 8)
            t[j][tx] = ip[(size_t)(r0 + j) * C + ch + tx];
        __syncthreads();
        __half2 p0 = __floats2half2_rn(t[rr][cc], t[rr + 1][cc]);
        __half2 p1 = __floats2half2_rn(t[rr + 2][cc], t[rr + 3][cc]);
        size_t off = (size_t)(ch + cc) * R + r0 + rr;
        *(uint2*)(op + off) = make_uint2(*(uint32_t*)&p0, *(uint32_t*)&p1);
        __syncthreads();
    }
}

// -------- warp-mma GEMM: C[M,N] = A[M,K] @ B[N,K]^T, single fp16 ----------
#define CTA_M 128
#define CTA_N 128
#define CTA_K 64
#define NTHREADS 128
#define ARR_BYTES (128 * 128)       // 128 rows x 128B (64 halves) = 16 KB
#define STAGE_BYTES (2 * ARR_BYTES) // A, B = 32 KB
#define NSTAGES 3
#define SMEM_TOTAL (NSTAGES * STAGE_BYTES)  // 96 KB -> 2 CTAs/SM

template <bool FUSE_GELU>
__global__ __launch_bounds__(NTHREADS, 2)
void gemm_wm(const __half* __restrict__ A0, const __half* __restrict__ B0,
             float* __restrict__ Cf, __half* __restrict__ Ch,
             int M, int N, int K) {
    extern __shared__ __align__(1024) char smem[];
    uint32_t sb = smem_u32(smem);
    const int tid = threadIdx.x, warp = tid >> 5, lid = tid & 31;
    const int e = blockIdx.z;
    const int m0 = blockIdx.y * CTA_M, n0 = blockIdx.x * CTA_N;
    const int wm = (warp >> 1) * 64;    // 2 warp rows x 64
    const int wn = (warp & 1) * 64;     // 2 warp cols x 64
    const int g = lid >> 2, q = lid & 3;

    size_t eA = (size_t)e * M * K, eB = (size_t)e * N * K;
    const __half* gA = A0 + eA + (size_t)m0 * K;
    const __half* gB = B0 + eB + (size_t)n0 * K;

    float acc[4][8][4];
#pragma unroll
    for (int mi = 0; mi < 4; mi++)
#pragma unroll
        for (int ni = 0; ni < 8; ni++)
#pragma unroll
            for (int k2 = 0; k2 < 4; k2++) acc[mi][ni][k2] = 0.0f;

    auto load_stage = [&](int kt, int s) {
        uint32_t st = sb + s * STAGE_BYTES;
        int k0 = kt * CTA_K;
#pragma unroll
        for (int i = 0; i < 8; i++) {
            int c = i * NTHREADS + tid;
            int row = c >> 3, h = c & 7;
            uint32_t sw = SWZ((uint32_t)(row * 128 + h * 16));
            size_t go = (size_t)row * K + k0 + h * 8;
            cp16(st + sw, gA + go);
            cp16(st + ARR_BYTES + sw, gB + go);
        }
    };

    auto compute = [&](int s) {
        uint32_t aA = sb + s * STAGE_BYTES;
        uint32_t bB = aA + ARR_BYTES;
#pragma unroll
        for (int kk = 0; kk < CTA_K; kk += 16) {
            uint32_t av[4][4], bb[8][2];
            {
                int arow = wm + (lid & 15);
                uint32_t acol = (uint32_t)(kk * 2 + (lid >> 4) * 16);
#pragma unroll
                for (int mi = 0; mi < 4; mi++) {
                    uint32_t ad = SWZ((uint32_t)((arow + mi * 16) * 128) + acol);
                    LDSM_X4(av[mi][0], av[mi][1], av[mi][2], av[mi][3], aA + ad);
                }
            }
            {
                int brow = wn + ((lid >> 4) & 1) * 8 + (lid & 7);
                uint32_t bcol = (uint32_t)(kk * 2 + ((lid >> 3) & 1) * 16);
#pragma unroll
                for (int nf = 0; nf < 4; nf++) {
                    uint32_t ad = SWZ((uint32_t)((brow + nf * 16) * 128) + bcol);
                    LDSM_X4(bb[nf * 2][0], bb[nf * 2][1], bb[nf * 2 + 1][0], bb[nf * 2 + 1][1],
                            bB + ad);
                }
            }
#pragma unroll
            for (int mi = 0; mi < 4; mi++)
#pragma unroll
                for (int ni = 0; ni < 8; ni++) mma16816(acc[mi][ni], av[mi], bb[ni]);
        }
    };

    const int NK = K / CTA_K;
    load_stage(0, 0);
    cp_commit();
    load_stage(1, 1);
    cp_commit();

    for (int kt = 0; kt < NK; kt++) {
        int s = kt % NSTAGES;
        cp_wait<1>();           // stage kt loads complete (1 younger group pending)
        __syncthreads();        // data visible; next-load stage free (compute(kt-1) done)
        if (kt + 2 < NK) load_stage(kt + 2, (kt + 2) % NSTAGES);
        cp_commit();            // commit every iter (possibly empty) to keep count
        compute(s);
    }

    // ---- epilogue ----
#pragma unroll
    for (int mi = 0; mi < 4; mi++) {
#pragma unroll
        for (int ni = 0; ni < 8; ni++) {
            int r = m0 + wm + mi * 16 + g;
            int col = n0 + wn + ni * 8 + q * 2;
            size_t o0 = ((size_t)e * M + r) * N + col;
            size_t o1 = o0 + (size_t)8 * N;
            float v0 = acc[mi][ni][0], v1 = acc[mi][ni][1];
            float v2 = acc[mi][ni][2], v3 = acc[mi][ni][3];
            if (FUSE_GELU) {
                v0 = gelu_tanh_f(v0); v1 = gelu_tanh_f(v1);
                v2 = gelu_tanh_f(v2); v3 = gelu_tanh_f(v3);
                __half2 p0 = __floats2half2_rn(v0, v1);
                __half2 p1 = __floats2half2_rn(v2, v3);
                *(__half2*)(Ch + o0) = p0;
                *(__half2*)(Ch + o1) = p1;
            } else {
                *(float2*)(Cf + o0) = make_float2(v0, v1);
                *(float2*)(Cf + o1) = make_float2(v2, v3);
            }
        }
    }
}

// -------- host launch --------
extern "C" void kernel_launch(void* const* d_in, const int* in_sizes, int n_in,
                              void* d_out, int out_size) {
    const float* x = (const float*)d_in[0];
    const float* w1 = (const float*)d_in[1];
    const float* w2 = (const float*)d_in[2];
    float* out = (float*)d_out;

    __half *x16, *w1t, *w2t, *h16;
    cudaGetSymbolAddress((void**)&x16, g_x16);
    cudaGetSymbolAddress((void**)&w1t, g_w1t);
    cudaGetSymbolAddress((void**)&w2t, g_w2t);
    cudaGetSymbolAddress((void**)&h16, g_h16);

    cudaFuncSetAttribute(gemm_wm<true>, cudaFuncAttributeMaxDynamicSharedMemorySize, SMEM_TOTAL);
    cudaFuncSetAttribute(gemm_wm<false>, cudaFuncAttributeMaxDynamicSharedMemorySize, SMEM_TOTAL);

    // pre-pass: x convert + single fused dual-weight transpose kernel
    size_t nx4 = (size_t)E_ * T_ * H_ / 4;
    conv16_k<<<(unsigned)((nx4 + 255) / 256), 256>>>(x, x16, nx4);
    // blocks per weight: (C/64) * (R/32) = (4096/64)*(1024/32) = 2048 (same both ways)
    tconv2<<<dim3((F_ / 64) * (H_ / 32), 1, 2 * E_), dim3(32, 8)>>>(w1, w2, w1t, w2t);

    // GEMM1 + GELU: A=x fp16 [T,H], B=w1^T fp16 [F,H] -> h fp16 [T,F]
    gemm_wm<true><<<dim3(F_ / CTA_N, T_ / CTA_M, E_), NTHREADS, SMEM_TOTAL>>>(
        x16, w1t, nullptr, h16, T_, F_, H_);
    // GEMM2: A=h fp16 [T,F], B=w2^T fp16 [H,F] -> out fp32 [T,H]
    gemm_wm<false><<<dim3(H_ / CTA_N, T_ / CTA_M, E_), NTHREADS, SMEM_TOTAL>>>(
        h16, w2t, out, nullptr, T_, H_, F_);
}